// round 14
// baseline (speedup 1.0000x reference)
#include <cuda_runtime.h>
#include <cstdint>

#define BATCH 512
#define TSEQ  64
#define P_DIM 8
#define Q_DIM 24
#define N_DIM 32
#define PQ    (P_DIM * Q_DIM)   // 192
#define SXP   28                // padded row stride for sx  (8 x 28)
#define SXTP  12                // padded row stride for sxT (24 x 12)
#define CPAD  36                // padded column stride (words) for 32-row panels
#define RPAD  12                // padded row stride for row-major 32x8 panels

// Scratch (no cudaMalloc allowed)
__device__ float g_U[2 * BATCH * N_DIM * P_DIM];  // 1024 x (32x8) row-major panels
__device__ int   g_cnt[BATCH];                    // arrival counters (parity, never reset)

// ---------------------------------------------------------------------------
// seq_kernel: one 128-thread block per (batch, q/a) panel. 1024 blocks.
//
// Quadratic Cayley recurrence (error 2||X||^3 ~ 1e-6/step):
//   G  = X C ;  C' = C - 2G + 2XG
// X = [[0, x],[-x^T, 0]], x = 8x24. C = 32x8 panel, column-major (CPAD).
//
// tp < 64 "top" owns entry (r=tp>>3, c=tp&7); tp >= 64 "bottom" owns rows
// 8+3*jg+{0,1,2}, col c.
//
// x staging: COALESCED loads (thread tp loads linear elements tp / tp+128 of
// the 192-float token row -> 1 L1 wavefront per warp-load), then committed to
// both shared layouts: sx row-major (SXP=28, <=2-way STS banks) and sxT
// transposed (SXTP=12, <=3-way STS banks; readers broadcast, conflict-free).
// Tail: second block of each batch (atomic parity) computes the distance.
// ---------------------------------------------------------------------------
__global__ __launch_bounds__(128) void seq_kernel(
    const int*   __restrict__ s1,
    const int*   __restrict__ s2,
    const float* __restrict__ emb_q,
    const float* __restrict__ emb_a,
    const float* __restrict__ transforms,
    const float* __restrict__ bias,
    const float* __restrict__ wf,
    const float* __restrict__ wb,
    float*       __restrict__ out)
{
    const int bid   = blockIdx.x;
    const bool is_q = (bid < BATCH);
    const int  b    = is_q ? bid : (bid - BATCH);
    const int  tp   = threadIdx.x;
    const bool top  = (tp < 64);

    const float* emb  = is_q ? emb_q : emb_a;
    const int*   sent = is_q ? s1    : s2;

    __shared__ __align__(16) float sx [2][8 * SXP];    // row-major padded 8x28
    __shared__ __align__(16) float sxT[2][24 * SXTP];  // transposed padded 24x12
    __shared__ __align__(16) float sC[8 * CPAD];       // column-major padded
    __shared__ __align__(16) float sG[8 * CPAD];
    __shared__ int stok[TSEQ];                         // token BYTE offsets
    // tail scratch
    __shared__ __align__(16) float sQ [N_DIM * RPAD];
    __shared__ __align__(16) float sCa[N_DIM * RPAD];
    __shared__ __align__(16) float sUq[N_DIM * RPAD];
    __shared__ __align__(16) float syb[N_DIM * CPAD];
    __shared__ float sA8[8 * 16];
    __shared__ float sW8[PQ];
    __shared__ float sbias[PQ];
    __shared__ float red[4];
    __shared__ int   s_old;

    // compute geometry
    const int c  = tp & 7;
    const int r  = tp >> 3;            // top only
    const int jg = (tp - 64) >> 3;     // bottom only
    const int j0 = 3 * jg;

    // coalesced-load element indices and their commit addresses
    const int iA = tp / Q_DIM, jA = tp % Q_DIM;          // element tp
    const int sxA = iA * SXP  + jA;
    const int txA = jA * SXTP + iA;
    const int eB = tp + 128;                              // top only
    const int iB = eB / Q_DIM, jB = eB % Q_DIM;
    const int sxB = iB * SXP  + jB;
    const int txB = jB * SXTP + iB;

    // transform factors on the linear elements (answer: identity)
    float tfA = 1.0f, tfB = 1.0f;
    if (is_q) {
        tfA = transforms[tp];
        if (top) tfB = transforms[eB];
    }

    // element pointers (byte-offset addressing per step)
    const char* pe1 = (const char*)(emb + tp);
    const char* pe2 = (const char*)(emb + eB);

    if (tp < TSEQ) stok[tp] = sent[b * TSEQ + tp] * (PQ * 4);

    // registers: own panel entries (top uses cown0 only)
    float cown0 = 0.f, cown1 = 0.f, cown2 = 0.f;
    if (top) cown0 = (r == c) ? 1.0f : 0.0f;

    // init shared C
    if (top) {
        sC[c * CPAD + r] = cown0;
    } else {
        sC[c * CPAD + 8 + j0 + 0] = 0.0f;
        sC[c * CPAD + 8 + j0 + 1] = 0.0f;
        sC[c * CPAD + 8 + j0 + 2] = 0.0f;
    }
    __syncthreads();

    // first x (t = 63) into buffer 1, both layouts, coalesced loads
    {
        int off = stok[TSEQ - 1];
        float vA = *(const float*)(pe1 + off) * tfA;
        sx [1][sxA] = vA;
        sxT[1][txA] = vA;
        if (top) {
            float vB = *(const float*)(pe2 + off) * tfB;
            sx [1][sxB] = vB;
            sxT[1][txB] = vB;
        }
    }
    __syncthreads();

    float rx[24];

#define SEQ_STEP(BUF, T)                                                        \
    do {                                                                        \
        float vA = 0.f, vB = 0.f;                                               \
        if ((T) > 0) {                                                          \
            int off = stok[(T) - 1];                                            \
            vA = *(const float*)(pe1 + off);                                    \
            if (top) vB = *(const float*)(pe2 + off);                           \
        }                                                                       \
        if (top) {                                                              \
            const float4* px = (const float4*)(sx[BUF] + r * SXP);              \
            _Pragma("unroll")                                                   \
            for (int m = 0; m < 6; ++m) {                                       \
                float4 v = px[m];                                               \
                rx[4*m]=v.x; rx[4*m+1]=v.y; rx[4*m+2]=v.z; rx[4*m+3]=v.w;       \
            }                                                                   \
        } else {                                                                \
            _Pragma("unroll")                                                   \
            for (int d = 0; d < 3; ++d) {                                       \
                const float4* pxt = (const float4*)(sxT[BUF] + (j0 + d) * SXTP);\
                float4 v0 = pxt[0], v1 = pxt[1];                                \
                rx[d*8+0]=v0.x; rx[d*8+1]=v0.y; rx[d*8+2]=v0.z; rx[d*8+3]=v0.w; \
                rx[d*8+4]=v1.x; rx[d*8+5]=v1.y; rx[d*8+6]=v1.z; rx[d*8+7]=v1.w; \
            }                                                                   \
        }                                                                       \
        float gown0, gown1 = 0.f, gown2 = 0.f;                                  \
        if (top) {                                                              \
            const float4* pc = (const float4*)(&sC[c * CPAD + 8]);              \
            float a0=0.f,a1=0.f,a2=0.f,a3=0.f;                                  \
            _Pragma("unroll")                                                   \
            for (int m = 0; m < 6; ++m) {                                       \
                float4 v = pc[m];                                               \
                a0 += rx[4*m]*v.x;  a1 += rx[4*m+1]*v.y;                        \
                a2 += rx[4*m+2]*v.z; a3 += rx[4*m+3]*v.w;                       \
            }                                                                   \
            gown0 = (a0 + a1) + (a2 + a3);                                      \
            sG[c * CPAD + r] = gown0;                                           \
        } else {                                                                \
            const float4* pc = (const float4*)(&sC[c * CPAD]);                  \
            float4 v0 = pc[0], v1 = pc[1];                                      \
            _Pragma("unroll")                                                   \
            for (int d = 0; d < 3; ++d) {                                       \
                float g = rx[d*8+0]*v0.x + rx[d*8+1]*v0.y + rx[d*8+2]*v0.z      \
                        + rx[d*8+3]*v0.w + rx[d*8+4]*v1.x + rx[d*8+5]*v1.y      \
                        + rx[d*8+6]*v1.z + rx[d*8+7]*v1.w;                      \
                g = -g;                                                         \
                if (d == 0) gown0 = g; else if (d == 1) gown1 = g; else gown2 = g;\
                sG[c * CPAD + 8 + j0 + d] = g;                                  \
            }                                                                   \
        }                                                                       \
        __syncthreads();                                                        \
        if (top) {                                                              \
            const float4* pg = (const float4*)(&sG[c * CPAD + 8]);              \
            float a0=0.f,a1=0.f,a2=0.f,a3=0.f;                                  \
            _Pragma("unroll")                                                   \
            for (int m = 0; m < 6; ++m) {                                       \
                float4 v = pg[m];                                               \
                a0 += rx[4*m]*v.x;  a1 += rx[4*m+1]*v.y;                        \
                a2 += rx[4*m+2]*v.z; a3 += rx[4*m+3]*v.w;                       \
            }                                                                   \
            float h = (a0 + a1) + (a2 + a3);                                    \
            cown0 += 2.0f * (h - gown0);                                        \
            sC[c * CPAD + r] = cown0;                                           \
        } else {                                                                \
            const float4* pg = (const float4*)(&sG[c * CPAD]);                  \
            float4 v0 = pg[0], v1 = pg[1];                                      \
            _Pragma("unroll")                                                   \
            for (int d = 0; d < 3; ++d) {                                       \
                float h = rx[d*8+0]*v0.x + rx[d*8+1]*v0.y + rx[d*8+2]*v0.z      \
                        + rx[d*8+3]*v0.w + rx[d*8+4]*v1.x + rx[d*8+5]*v1.y      \
                        + rx[d*8+6]*v1.z + rx[d*8+7]*v1.w;                      \
                h = -h;                                                         \
                float go = (d == 0) ? gown0 : ((d == 1) ? gown1 : gown2);       \
                float cn = ((d == 0) ? cown0 : ((d == 1) ? cown1 : cown2))      \
                           + 2.0f * (h - go);                                   \
                if (d == 0) cown0 = cn; else if (d == 1) cown1 = cn; else cown2 = cn;\
                sC[c * CPAD + 8 + j0 + d] = cn;                                 \
            }                                                                   \
        }                                                                       \
        if ((T) > 0) {                                                          \
            float wA = vA * tfA;                                                \
            sx [(BUF)^1][sxA] = wA;                                             \
            sxT[(BUF)^1][txA] = wA;                                             \
            if (top) {                                                          \
                float wB = vB * tfB;                                            \
                sx [(BUF)^1][sxB] = wB;                                         \
                sxT[(BUF)^1][txB] = wB;                                         \
            }                                                                   \
        }                                                                       \
        __syncthreads();                                                        \
    } while (0)

    for (int t2 = 31; t2 >= 0; --t2) {
        SEQ_STEP(1, 2 * t2 + 1);
        SEQ_STEP(0, 2 * t2);
    }
#undef SEQ_STEP

    // write final panel row-major to global
    {
        int idx = tp;
        g_U[(size_t)bid * 256 + idx] = sC[(idx & 7) * CPAD + (idx >> 3)];
        idx = tp + 128;
        g_U[(size_t)bid * 256 + idx] = sC[(idx & 7) * CPAD + (idx >> 3)];
    }

    // ---- arrival protocol: second block of this batch runs the distance tail
    __threadfence();              // release g_U writes
    __syncthreads();
    if (tp == 0) s_old = atomicAdd(&g_cnt[b], 1);
    __syncthreads();
    if ((s_old & 1) == 0) return; // first arrival: done
    __threadfence();              // acquire peer's g_U writes

    // =====================  DISTANCE TAIL (128 threads)  =====================
    #pragma unroll
    for (int k = 0; k < 2; ++k) {
        int idx = tp + 128 * k;
        int rr = idx >> 3, cc = idx & 7;
        sQ [rr * RPAD + cc] = g_U[(size_t)b * 256 + idx];
        sCa[rr * RPAD + cc] = g_U[(size_t)(BATCH + b) * 256 + idx];
    }
    for (int i = tp; i < PQ; i += 128) sbias[i] = bias[i];
    __syncthreads();

    // A = [I + b b^T | I]
    {
        int i = tp >> 4, cc = tp & 15;
        float v;
        if (cc < 8) {
            v = (i == cc) ? 1.0f : 0.0f;
            #pragma unroll
            for (int k = 0; k < Q_DIM; ++k) v += sbias[i * Q_DIM + k] * sbias[cc * Q_DIM + k];
        } else {
            v = (i == cc - 8) ? 1.0f : 0.0f;
        }
        sA8[i * 16 + cc] = v;
    }
    __syncthreads();

    // Gauss-Jordan (SPD, pivots >= 1)
    for (int k = 0; k < 8; ++k) {
        int i = tp >> 4, cc = tp & 15;
        float piv = 1.0f / sA8[k * 16 + k];
        float akc = sA8[k * 16 + cc] * piv;
        float nv = (i == k) ? akc : (sA8[i * 16 + cc] - sA8[i * 16 + k] * akc);
        __syncthreads();
        sA8[i * 16 + cc] = nv;
        __syncthreads();
    }

    // W = K b
    for (int idx = tp; idx < PQ; idx += 128) {
        int i = idx / Q_DIM, jj = idx % Q_DIM;
        float w = 0.0f;
        #pragma unroll
        for (int k = 0; k < 8; ++k) w += sA8[i * 16 + 8 + k] * sbias[k * Q_DIM + jj];
        sW8[idx] = w;
    }
    __syncthreads();

    // yb = [[2K - I, -2W], [2W^T, I - 2 b^T W]]
    #pragma unroll
    for (int e = 0; e < 8; ++e) {
        int idx = tp + 128 * e;
        int rr = idx >> 5, cc = idx & 31;
        float y;
        if (rr < 8 && cc < 8) {
            y = 2.0f * sA8[rr * 16 + 8 + cc] - ((rr == cc) ? 1.0f : 0.0f);
        } else if (rr < 8) {
            y = -2.0f * sW8[rr * Q_DIM + (cc - 8)];
        } else if (cc < 8) {
            y = 2.0f * sW8[cc * Q_DIM + (rr - 8)];
        } else {
            int jj = rr - 8, c2 = cc - 8;
            float acc = 0.0f;
            #pragma unroll
            for (int i = 0; i < 8; ++i) acc += sbias[i * Q_DIM + jj] * sW8[i * Q_DIM + c2];
            y = ((jj == c2) ? 1.0f : 0.0f) - 2.0f * acc;
        }
        syb[rr * CPAD + cc] = y;
    }
    __syncthreads();

    // Uq = yb * Q
    #pragma unroll
    for (int k2 = 0; k2 < 2; ++k2) {
        int idx = tp + 128 * k2;
        int rr = idx >> 3, cc = idx & 7;
        float acc = 0.0f;
        #pragma unroll
        for (int k = 0; k < N_DIM; ++k)
            acc += syb[rr * CPAD + k] * sQ[k * RPAD + cc];
        sUq[rr * RPAD + cc] = acc;
    }
    __syncthreads();

    // dist^2 = || Uq Uq^T - Ca Ca^T ||_F^2
    float acc = 0.0f;
    #pragma unroll
    for (int e = 0; e < 8; ++e) {
        int idx = tp + 128 * e;
        int i = idx >> 5, jj = idx & 31;
        const float4* ui = (const float4*)(&sUq[i  * RPAD]);
        const float4* uj = (const float4*)(&sUq[jj * RPAD]);
        const float4* ai = (const float4*)(&sCa[i  * RPAD]);
        const float4* aj = (const float4*)(&sCa[jj * RPAD]);
        float d = 0.0f;
        #pragma unroll
        for (int m = 0; m < 2; ++m) {
            float4 a = ui[m], bq = uj[m], x = ai[m], y = aj[m];
            d += a.x * bq.x + a.y * bq.y + a.z * bq.z + a.w * bq.w;
            d -= x.x * y.x  + x.y * y.y  + x.z * y.z  + x.w * y.w;
        }
        acc += d * d;
    }

    #pragma unroll
    for (int off = 16; off > 0; off >>= 1)
        acc += __shfl_xor_sync(0xFFFFFFFFu, acc, off);
    if ((tp & 31) == 0) red[tp >> 5] = acc;
    __syncthreads();
    if (tp == 0) {
        float s = red[0] + red[1] + red[2] + red[3];
        out[b] = -(*wf) * sqrtf(s) + (*wb);
    }
}

// ---------------------------------------------------------------------------
extern "C" void kernel_launch(void* const* d_in, const int* in_sizes, int n_in,
                              void* d_out, int out_size)
{
    const int*   s1 = (const int*)  d_in[0];   // sentence_1 [512,64]
    const int*   s2 = (const int*)  d_in[1];   // sentence_2 [512,64]
    const float* qe = (const float*)d_in[2];   // question_embedding [32000,8,24]
    const float* ae = (const float*)d_in[3];   // answer_embedding   [32000,8,24]
    const float* qt = (const float*)d_in[4];   // question_transforms [8,24]
    const float* qb = (const float*)d_in[5];   // question_bias [8,24]
    const float* wf = (const float*)d_in[6];
    const float* wb = (const float*)d_in[7];
    float* out = (float*)d_out;

    seq_kernel<<<2 * BATCH, 128>>>(s1, s2, qe, ae, qt, qb, wf, wb, out);
}

// round 15
// speedup vs baseline: 1.0847x; 1.0847x over previous
#include <cuda_runtime.h>
#include <cstdint>

#define BATCH 512
#define TSEQ  64
#define P_DIM 8
#define Q_DIM 24
#define N_DIM 32
#define PQ    (P_DIM * Q_DIM)   // 192
#define SXP   28                // padded row stride for sx  (8 x 28)
#define SXTP  12                // padded row stride for sxT (24 x 12)
#define CPAD  36                // padded column stride (words) for panels
#define RPAD  12                // tail: padded row stride for 32x8 panels

// Scratch (no cudaMalloc allowed)
__device__ float g_U[2 * BATCH * N_DIM * P_DIM];  // 1024 x (32x8) row-major panels
__device__ int   g_cnt[BATCH];                    // arrival counters (parity, never reset)

// ---------------------------------------------------------------------------
// seq_kernel: one 64-thread block per (batch, q/a) panel. 1024 blocks... x2.
//
// Quadratic Cayley recurrence (error 2||X||^3 ~ 1e-6/step):
//   G  = X C ;  C' = C - 2G + 2XG
// X = [[0, x],[-x^T, 0]], x = 8x24. C = 32x8 panel, column-major (CPAD).
//
// 2-column register blocking:
//   tid < 32 "top":    r = tid>>2, c4 = tid&3; owns (r,c4) and (r,c4+4).
//   tid >= 32 "bottom": jg = (tid-32)>>2, c4 = (tid-32)&3;
//                       owns rows 8+3jg+{0,1,2} x cols {c4, c4+4}.
// The x-slice registers serve BOTH columns -> ~27% fewer LDS instructions
// per panel-step at identical FLOP.
//
// x staging: coalesced (thread loads elements tid, tid+64, tid+128), committed
// to both layouts (sx row-major / sxT transposed), double-buffered.
// Tail: second block of each batch (atomic parity) computes the distance.
// ---------------------------------------------------------------------------
__global__ __launch_bounds__(64, 12) void seq_kernel(
    const int*   __restrict__ s1,
    const int*   __restrict__ s2,
    const float* __restrict__ emb_q,
    const float* __restrict__ emb_a,
    const float* __restrict__ transforms,
    const float* __restrict__ bias,
    const float* __restrict__ wf,
    const float* __restrict__ wb,
    float*       __restrict__ out)
{
    const int bid   = blockIdx.x;
    const bool is_q = (bid < BATCH);
    const int  b    = is_q ? bid : (bid - BATCH);
    const int  tp   = threadIdx.x;     // 0..63
    const bool top  = (tp < 32);

    const float* emb  = is_q ? emb_q : emb_a;
    const int*   sent = is_q ? s1    : s2;

    __shared__ __align__(16) float sx [2][8 * SXP];    // row-major padded 8x28
    __shared__ __align__(16) float sxT[2][24 * SXTP];  // transposed padded 24x12
    __shared__ __align__(16) float sC[8 * CPAD];       // column-major padded
    __shared__ __align__(16) float sG[8 * CPAD];
    __shared__ int stok[TSEQ];                         // token BYTE offsets
    // tail scratch
    __shared__ __align__(16) float sQ [N_DIM * RPAD];
    __shared__ __align__(16) float sCa[N_DIM * RPAD];
    __shared__ __align__(16) float sUq[N_DIM * RPAD];
    __shared__ __align__(16) float syb[N_DIM * CPAD];
    __shared__ float sA8[8 * 16];
    __shared__ float sW8[PQ];
    __shared__ float sbias[PQ];
    __shared__ float red[2];
    __shared__ int   s_old;

    // compute geometry
    const int c4 = top ? (tp & 3) : ((tp - 32) & 3);
    const int r  = tp >> 2;            // top only (0..7)
    const int jg = (tp - 32) >> 2;     // bottom only (0..7)
    const int j0 = 3 * jg;

    // x staging: 3 coalesced elements per thread
    int   sxA[3], txA[3];
    float tf[3];
    const char* pe[3];
    #pragma unroll
    for (int m = 0; m < 3; ++m) {
        int e  = tp + 64 * m;
        int ie = e / Q_DIM, je = e % Q_DIM;
        sxA[m] = ie * SXP  + je;
        txA[m] = je * SXTP + ie;
        tf[m]  = is_q ? transforms[e] : 1.0f;
        pe[m]  = (const char*)(emb + e);
    }

    stok[tp] = sent[b * TSEQ + tp] * (PQ * 4);

    // own panel entries: top cown[2] (cols c4, c4+4); bottom cown[6] (3 rows x 2 cols)
    float cown[6] = {0.f, 0.f, 0.f, 0.f, 0.f, 0.f};
    if (top) {
        cown[0] = (r == c4)     ? 1.0f : 0.0f;
        cown[1] = (r == c4 + 4) ? 1.0f : 0.0f;
        sC[c4 * CPAD + r]       = cown[0];
        sC[(c4 + 4) * CPAD + r] = cown[1];
    } else {
        #pragma unroll
        for (int cc = 0; cc < 2; ++cc) {
            int col = c4 + 4 * cc;
            sC[col * CPAD + 8 + j0 + 0] = 0.0f;
            sC[col * CPAD + 8 + j0 + 1] = 0.0f;
            sC[col * CPAD + 8 + j0 + 2] = 0.0f;
        }
    }
    __syncthreads();

    // first x (t = 63) into buffer 1, both layouts
    {
        int off = stok[TSEQ - 1];
        #pragma unroll
        for (int m = 0; m < 3; ++m) {
            float v = *(const float*)(pe[m] + off) * tf[m];
            sx [1][sxA[m]] = v;
            sxT[1][txA[m]] = v;
        }
    }
    __syncthreads();

    float rx[24];
    float gown[6];

#define SEQ_STEP(BUF, T)                                                        \
    do {                                                                        \
        float vn0 = 0.f, vn1 = 0.f, vn2 = 0.f;                                  \
        if ((T) > 0) {                                                          \
            int off = stok[(T) - 1];                                            \
            vn0 = *(const float*)(pe[0] + off);                                 \
            vn1 = *(const float*)(pe[1] + off);                                 \
            vn2 = *(const float*)(pe[2] + off);                                 \
        }                                                                       \
        if (top) {                                                              \
            const float4* px = (const float4*)(sx[BUF] + r * SXP);              \
            _Pragma("unroll")                                                   \
            for (int m = 0; m < 6; ++m) {                                       \
                float4 v = px[m];                                               \
                rx[4*m]=v.x; rx[4*m+1]=v.y; rx[4*m+2]=v.z; rx[4*m+3]=v.w;       \
            }                                                                   \
        } else {                                                                \
            _Pragma("unroll")                                                   \
            for (int d = 0; d < 3; ++d) {                                       \
                const float4* pxt = (const float4*)(sxT[BUF] + (j0 + d) * SXTP);\
                float4 v0 = pxt[0], v1 = pxt[1];                                \
                rx[d*8+0]=v0.x; rx[d*8+1]=v0.y; rx[d*8+2]=v0.z; rx[d*8+3]=v0.w; \
                rx[d*8+4]=v1.x; rx[d*8+5]=v1.y; rx[d*8+6]=v1.z; rx[d*8+7]=v1.w; \
            }                                                                   \
        }                                                                       \
        /* Phase 1: G = X C */                                                  \
        if (top) {                                                              \
            _Pragma("unroll")                                                   \
            for (int cc = 0; cc < 2; ++cc) {                                    \
                int col = c4 + 4 * cc;                                          \
                const float4* pc = (const float4*)(&sC[col * CPAD + 8]);        \
                float a0=0.f,a1=0.f,a2=0.f,a3=0.f;                              \
                _Pragma("unroll")                                               \
                for (int m = 0; m < 6; ++m) {                                   \
                    float4 v = pc[m];                                           \
                    a0 += rx[4*m]*v.x;  a1 += rx[4*m+1]*v.y;                    \
                    a2 += rx[4*m+2]*v.z; a3 += rx[4*m+3]*v.w;                   \
                }                                                               \
                gown[cc] = (a0 + a1) + (a2 + a3);                               \
                sG[col * CPAD + r] = gown[cc];                                  \
            }                                                                   \
        } else {                                                                \
            _Pragma("unroll")                                                   \
            for (int cc = 0; cc < 2; ++cc) {                                    \
                int col = c4 + 4 * cc;                                          \
                const float4* pc = (const float4*)(&sC[col * CPAD]);            \
                float4 v0 = pc[0], v1 = pc[1];                                  \
                _Pragma("unroll")                                               \
                for (int d = 0; d < 3; ++d) {                                   \
                    float g = rx[d*8+0]*v0.x + rx[d*8+1]*v0.y + rx[d*8+2]*v0.z  \
                            + rx[d*8+3]*v0.w + rx[d*8+4]*v1.x + rx[d*8+5]*v1.y  \
                            + rx[d*8+6]*v1.z + rx[d*8+7]*v1.w;                  \
                    g = -g;                                                     \
                    gown[cc*3+d] = g;                                           \
                    sG[col * CPAD + 8 + j0 + d] = g;                            \
                }                                                               \
            }                                                                   \
        }                                                                       \
        __syncthreads();                                                        \
        /* Phase 2: C' = C - 2G + 2XG */                                        \
        if (top) {                                                              \
            _Pragma("unroll")                                                   \
            for (int cc = 0; cc < 2; ++cc) {                                    \
                int col = c4 + 4 * cc;                                          \
                const float4* pg = (const float4*)(&sG[col * CPAD + 8]);        \
                float a0=0.f,a1=0.f,a2=0.f,a3=0.f;                              \
                _Pragma("unroll")                                               \
                for (int m = 0; m < 6; ++m) {                                   \
                    float4 v = pg[m];                                           \
                    a0 += rx[4*m]*v.x;  a1 += rx[4*m+1]*v.y;                    \
                    a2 += rx[4*m+2]*v.z; a3 += rx[4*m+3]*v.w;                   \
                }                                                               \
                float h = (a0 + a1) + (a2 + a3);                                \
                cown[cc] += 2.0f * (h - gown[cc]);                              \
                sC[col * CPAD + r] = cown[cc];                                  \
            }                                                                   \
        } else {                                                                \
            _Pragma("unroll")                                                   \
            for (int cc = 0; cc < 2; ++cc) {                                    \
                int col = c4 + 4 * cc;                                          \
                const float4* pg = (const float4*)(&sG[col * CPAD]);            \
                float4 v0 = pg[0], v1 = pg[1];                                  \
                _Pragma("unroll")                                               \
                for (int d = 0; d < 3; ++d) {                                   \
                    float h = rx[d*8+0]*v0.x + rx[d*8+1]*v0.y + rx[d*8+2]*v0.z  \
                            + rx[d*8+3]*v0.w + rx[d*8+4]*v1.x + rx[d*8+5]*v1.y  \
                            + rx[d*8+6]*v1.z + rx[d*8+7]*v1.w;                  \
                    h = -h;                                                     \
                    cown[cc*3+d] += 2.0f * (h - gown[cc*3+d]);                  \
                    sC[col * CPAD + 8 + j0 + d] = cown[cc*3+d];                 \
                }                                                               \
            }                                                                   \
        }                                                                       \
        if ((T) > 0) {                                                          \
            float w0 = vn0 * tf[0], w1 = vn1 * tf[1], w2 = vn2 * tf[2];         \
            sx [(BUF)^1][sxA[0]] = w0;  sxT[(BUF)^1][txA[0]] = w0;              \
            sx [(BUF)^1][sxA[1]] = w1;  sxT[(BUF)^1][txA[1]] = w1;              \
            sx [(BUF)^1][sxA[2]] = w2;  sxT[(BUF)^1][txA[2]] = w2;              \
        }                                                                       \
        __syncthreads();                                                        \
    } while (0)

    for (int t2 = 31; t2 >= 0; --t2) {
        SEQ_STEP(1, 2 * t2 + 1);
        SEQ_STEP(0, 2 * t2);
    }
#undef SEQ_STEP

    // write final panel row-major to global, straight from registers
    if (top) {
        g_U[(size_t)bid * 256 + r * 8 + c4]     = cown[0];
        g_U[(size_t)bid * 256 + r * 8 + c4 + 4] = cown[1];
    } else {
        #pragma unroll
        for (int cc = 0; cc < 2; ++cc) {
            int col = c4 + 4 * cc;
            #pragma unroll
            for (int d = 0; d < 3; ++d)
                g_U[(size_t)bid * 256 + (8 + j0 + d) * 8 + col] = cown[cc * 3 + d];
        }
    }

    // ---- arrival protocol: second block of this batch runs the distance tail
    __threadfence();              // release g_U writes
    __syncthreads();
    if (tp == 0) s_old = atomicAdd(&g_cnt[b], 1);
    __syncthreads();
    if ((s_old & 1) == 0) return; // first arrival: done
    __threadfence();              // acquire peer's g_U writes

    // =====================  DISTANCE TAIL (64 threads)  =====================
    #pragma unroll
    for (int k = 0; k < 4; ++k) {
        int idx = tp + 64 * k;
        int rr = idx >> 3, cc = idx & 7;
        sQ [rr * RPAD + cc] = g_U[(size_t)b * 256 + idx];
        sCa[rr * RPAD + cc] = g_U[(size_t)(BATCH + b) * 256 + idx];
    }
    #pragma unroll
    for (int k = 0; k < 3; ++k) sbias[tp + 64 * k] = bias[tp + 64 * k];
    __syncthreads();

    // A = [I + b b^T | I]
    #pragma unroll
    for (int k = 0; k < 2; ++k) {
        int idx = tp + 64 * k;
        int i = idx >> 4, cc = idx & 15;
        float v;
        if (cc < 8) {
            v = (i == cc) ? 1.0f : 0.0f;
            #pragma unroll
            for (int kk = 0; kk < Q_DIM; ++kk)
                v += sbias[i * Q_DIM + kk] * sbias[cc * Q_DIM + kk];
        } else {
            v = (i == cc - 8) ? 1.0f : 0.0f;
        }
        sA8[i * 16 + cc] = v;
    }
    __syncthreads();

    // Gauss-Jordan (SPD, pivots >= 1)
    for (int k = 0; k < 8; ++k) {
        float piv = 1.0f / sA8[k * 16 + k];
        float nv[2];
        #pragma unroll
        for (int q = 0; q < 2; ++q) {
            int idx = tp + 64 * q;
            int i = idx >> 4, cc = idx & 15;
            float akc = sA8[k * 16 + cc] * piv;
            nv[q] = (i == k) ? akc : (sA8[i * 16 + cc] - sA8[i * 16 + k] * akc);
        }
        __syncthreads();
        #pragma unroll
        for (int q = 0; q < 2; ++q) {
            int idx = tp + 64 * q;
            sA8[(idx >> 4) * 16 + (idx & 15)] = nv[q];
        }
        __syncthreads();
    }

    // W = K b
    #pragma unroll
    for (int q = 0; q < 3; ++q) {
        int idx = tp + 64 * q;
        int i = idx / Q_DIM, jj = idx % Q_DIM;
        float w = 0.0f;
        #pragma unroll
        for (int k = 0; k < 8; ++k) w += sA8[i * 16 + 8 + k] * sbias[k * Q_DIM + jj];
        sW8[idx] = w;
    }
    __syncthreads();

    // yb = [[2K - I, -2W], [2W^T, I - 2 b^T W]]
    #pragma unroll
    for (int e = 0; e < 16; ++e) {
        int idx = tp + 64 * e;
        int rr = idx >> 5, cc = idx & 31;
        float y;
        if (rr < 8 && cc < 8) {
            y = 2.0f * sA8[rr * 16 + 8 + cc] - ((rr == cc) ? 1.0f : 0.0f);
        } else if (rr < 8) {
            y = -2.0f * sW8[rr * Q_DIM + (cc - 8)];
        } else if (cc < 8) {
            y = 2.0f * sW8[cc * Q_DIM + (rr - 8)];
        } else {
            int jj = rr - 8, c2 = cc - 8;
            float acc = 0.0f;
            #pragma unroll
            for (int i = 0; i < 8; ++i) acc += sbias[i * Q_DIM + jj] * sW8[i * Q_DIM + c2];
            y = ((jj == c2) ? 1.0f : 0.0f) - 2.0f * acc;
        }
        syb[rr * CPAD + cc] = y;
    }
    __syncthreads();

    // Uq = yb * Q
    #pragma unroll
    for (int k2 = 0; k2 < 4; ++k2) {
        int idx = tp + 64 * k2;
        int rr = idx >> 3, cc = idx & 7;
        float acc = 0.0f;
        #pragma unroll
        for (int k = 0; k < N_DIM; ++k)
            acc += syb[rr * CPAD + k] * sQ[k * RPAD + cc];
        sUq[rr * RPAD + cc] = acc;
    }
    __syncthreads();

    // dist^2 = || Uq Uq^T - Ca Ca^T ||_F^2
    float acc = 0.0f;
    #pragma unroll
    for (int e = 0; e < 16; ++e) {
        int idx = tp + 64 * e;
        int i = idx >> 5, jj = idx & 31;
        const float4* ui = (const float4*)(&sUq[i  * RPAD]);
        const float4* uj = (const float4*)(&sUq[jj * RPAD]);
        const float4* ai = (const float4*)(&sCa[i  * RPAD]);
        const float4* aj = (const float4*)(&sCa[jj * RPAD]);
        float d = 0.0f;
        #pragma unroll
        for (int m = 0; m < 2; ++m) {
            float4 a = ui[m], bq = uj[m], x = ai[m], y = aj[m];
            d += a.x * bq.x + a.y * bq.y + a.z * bq.z + a.w * bq.w;
            d -= x.x * y.x  + x.y * y.y  + x.z * y.z  + x.w * y.w;
        }
        acc += d * d;
    }

    #pragma unroll
    for (int off = 16; off > 0; off >>= 1)
        acc += __shfl_xor_sync(0xFFFFFFFFu, acc, off);
    if ((tp & 31) == 0) red[tp >> 5] = acc;
    __syncthreads();
    if (tp == 0) {
        float s = red[0] + red[1];
        out[b] = -(*wf) * sqrtf(s) + (*wb);
    }
}

// ---------------------------------------------------------------------------
extern "C" void kernel_launch(void* const* d_in, const int* in_sizes, int n_in,
                              void* d_out, int out_size)
{
    const int*   s1 = (const int*)  d_in[0];   // sentence_1 [512,64]
    const int*   s2 = (const int*)  d_in[1];   // sentence_2 [512,64]
    const float* qe = (const float*)d_in[2];   // question_embedding [32000,8,24]
    const float* ae = (const float*)d_in[3];   // answer_embedding   [32000,8,24]
    const float* qt = (const float*)d_in[4];   // question_transforms [8,24]
    const float* qb = (const float*)d_in[5];   // question_bias [8,24]
    const float* wf = (const float*)d_in[6];
    const float* wb = (const float*)d_in[7];
    float* out = (float*)d_out;

    seq_kernel<<<2 * BATCH, 64>>>(s1, s2, qe, ae, qt, qb, wf, wb, out);
}